// round 15
// baseline (speedup 1.0000x reference)
#include <cuda_runtime.h>
#include <cuda_fp16.h>
#include <cstdint>

// ---------------------------------------------------------------------------
// CompositeGraphNetWithFC on GB300 (sm_103 PTX -> mma.sync HMMA)
// R15: R13 schedule (2 streams) + dis-fold (R14) + quad-paired gathers
//      (4 edges in flight per warp, 8 lanes x 2 uint4 each -> MLP 4x).
// ---------------------------------------------------------------------------

#define NN 100000
#define NE 1600000
#define NM 10000
#define NI 800000
#define FD 128

#define ECAP 64
#define HCAP 160
#define NCAP 40

// ---- scratch ----
__device__ __align__(16) __half g_Hh [(size_t)NN * FD];
__device__ __align__(16) __half g_H2h[(size_t)NN * FD];
__device__ __align__(16) __half g_EFh[(size_t)NM * FD];
__device__ __align__(16) __half g_X1h[(size_t)NN * FD];
__device__ __align__(16) __half g_X2h[(size_t)NN * FD];
__device__ __align__(16) __half g_PARTh[(size_t)NN * FD];
__device__ float g_dis [NN];
__device__ float g_nhw [NN];
__device__ float g_Dinv[NN];
__device__ float g_Binv[NM];
__device__ int   g_ecnt[NN], g_hcnt[NM], g_ncnt[NN];
__device__ __align__(8) int2 g_ebkt[(size_t)NN * ECAP];
__device__ int   g_hbkt[(size_t)NM * HCAP];
__device__ int   g_nbkt[(size_t)NN * NCAP];
__device__ __align__(16) __half g_Wt[6 * FD * FD];

struct StreamInit {
    cudaStream_t s1 = 0;
    cudaEvent_t evFork = 0, evW = 0, evCSR = 0, evHyp = 0;
    bool ok = false;
    StreamInit() {
        ok = (cudaStreamCreateWithFlags(&s1, cudaStreamNonBlocking) == cudaSuccess)
          && (cudaEventCreateWithFlags(&evFork, cudaEventDisableTiming) == cudaSuccess)
          && (cudaEventCreateWithFlags(&evW,    cudaEventDisableTiming) == cudaSuccess)
          && (cudaEventCreateWithFlags(&evCSR,  cudaEventDisableTiming) == cudaSuccess)
          && (cudaEventCreateWithFlags(&evHyp,  cudaEventDisableTiming) == cudaSuccess);
        if (!ok) s1 = 0;
    }
};
static StreamInit g_si;

__device__ __forceinline__ float2 h2f(uint32_t u) {
    return __half22float2(*reinterpret_cast<__half2*>(&u));
}
__device__ __forceinline__ uint32_t f2h(float a, float b) {
    __half2 h = __floats2half2_rn(a, b);
    return *reinterpret_cast<uint32_t*>(&h);
}
__device__ __forceinline__ void acc8(float* acc, uint4 u, float w) {
    float2 p0 = h2f(u.x), p1 = h2f(u.y), p2 = h2f(u.z), p3 = h2f(u.w);
    acc[0] += w * p0.x; acc[1] += w * p0.y;
    acc[2] += w * p1.x; acc[3] += w * p1.y;
    acc[4] += w * p2.x; acc[5] += w * p2.y;
    acc[6] += w * p3.x; acc[7] += w * p3.y;
}

// ---------------------------------------------------------------------------
// weight conversion
// ---------------------------------------------------------------------------
__global__ void k_wconv(const float* __restrict__ Wg1, const float* __restrict__ Wg2,
                        const float* __restrict__ Wh1, const float* __restrict__ Wh2,
                        const float* __restrict__ Wfc) {
    int idx = blockIdx.x * 256 + threadIdx.x;
    if (idx >= 6 * FD * FD) return;
    int b = idx >> 14, e = idx & 16383, n = e >> 7, k = e & 127;
    float w;
    switch (b) {
        case 0: w = Wg1[k * FD + n]; break;
        case 1: w = Wg2[k * FD + n]; break;
        case 2: w = Wh1[k * FD + n]; break;
        case 3: w = Wh2[k * FD + n]; break;
        case 4: w = Wfc[k * FD + n]; break;
        default: w = Wfc[(k + FD) * FD + n]; break;
    }
    g_Wt[idx] = __float2half_rn(w);
}

// ---------------------------------------------------------------------------
// prep (combined, R13 style)
// ---------------------------------------------------------------------------
__global__ void k_init() {
    int i = blockIdx.x * 256 + threadIdx.x;
    if (i < NN) { g_ecnt[i] = 0; g_ncnt[i] = 0; }
    if (i < NM) { g_hcnt[i] = 0; }
}
__global__ void k_build(const int* __restrict__ erow, const int* __restrict__ ecol,
                        const float* __restrict__ ew,
                        const int* __restrict__ ni, const int* __restrict__ hi) {
    int idx = blockIdx.x * 256 + threadIdx.x;
    if (idx < NE) {
        int r = erow[idx], c = ecol[idx];
        float w = ew[idx];
        int p = atomicAdd(&g_ecnt[c], 1);
        if (p < ECAP) g_ebkt[(size_t)c * ECAP + p] = make_int2(r, __float_as_int(w));
    } else if (idx < NE + NI) {
        int i = idx - NE;
        int n = ni[i], h = hi[i];
        int p = atomicAdd(&g_hcnt[h], 1);
        if (p < HCAP) g_hbkt[(size_t)h * HCAP + p] = n;
        int q = atomicAdd(&g_ncnt[n], 1);
        if (q < NCAP) g_nbkt[(size_t)n * NCAP + q] = h;
    }
}
__global__ void k_prep_fin(const float* __restrict__ hd) {
    int i = blockIdx.x * 256 + threadIdx.x;
    if (i < NN) {
        int ec = min(g_ecnt[i], ECAP);
        float deg = 1.0f;
        for (int j = 0; j < ec; ++j)
            deg += __int_as_float(g_ebkt[(size_t)i * ECAP + j].y);
        g_dis[i] = rsqrtf(deg);
        int nc_raw = g_ncnt[i];
        int nc = min(nc_raw, NCAP);
        float nh = 0.0f;
        for (int j = 0; j < nc; ++j)
            nh += hd[g_nbkt[(size_t)i * NCAP + j]];
        g_nhw[i] = nh;
        g_Dinv[i] = nc_raw > 0 ? 1.0f / (float)nc_raw : 0.0f;
    }
    if (i < NM) {
        int b = g_hcnt[i];
        g_Binv[i] = b > 0 ? 1.0f / (float)b : 0.0f;
    }
}

// ---------------------------------------------------------------------------
// GEMM: 64-row tile x 128, single-product fp16 mma + ldmatrix
//   OSC: epilogue scales output rows by oscale[row] (fp16 out path)
// ---------------------------------------------------------------------------
#define GP 136
#define OFF_A 0
#define OFF_B (64 * GP * 2)
#define GSMEM (OFF_B + 128 * GP * 2)    // 52224 bytes
#define SP 132

__device__ __forceinline__ void mma_f16(float* d, const uint32_t* a,
                                        uint32_t b0, uint32_t b1) {
    asm volatile(
        "mma.sync.aligned.m16n8k16.row.col.f32.f16.f16.f32 "
        "{%0,%1,%2,%3}, {%4,%5,%6,%7}, {%8,%9}, {%0,%1,%2,%3};"
        : "+f"(d[0]), "+f"(d[1]), "+f"(d[2]), "+f"(d[3])
        : "r"(a[0]), "r"(a[1]), "r"(a[2]), "r"(a[3]), "r"(b0), "r"(b1));
}
__device__ __forceinline__ void ldsm4(uint32_t* r, uint32_t a) {
    asm volatile("ldmatrix.sync.aligned.m8n8.x4.shared.b16 {%0,%1,%2,%3}, [%4];"
                 : "=r"(r[0]), "=r"(r[1]), "=r"(r[2]), "=r"(r[3]) : "r"(a));
}

template<int EPI, bool SCALE, bool ADDC, bool OUTH, bool AHALF, bool OSC>
__global__ void __launch_bounds__(256, 4) k_gemm(
    const void* __restrict__ Av,
    const __half* __restrict__ B,
    const float* __restrict__ rowscale, const float* __restrict__ bias,
    const __half* __restrict__ C0,
    void* __restrict__ OutV,
    const float* __restrict__ Wo, const float* __restrict__ bo,
    const float* __restrict__ oscale)
{
    extern __shared__ char sm[];
    const int tid = threadIdx.x, lane = tid & 31, wid = tid >> 5;
    const int row0 = blockIdx.x << 6;
    const int m0 = (wid & 1) << 5, n0 = (wid >> 1) << 5;
    const int lr = lane >> 2, lc = lane & 3;

    // stage A
    if (AHALF) {
        const __half* A = (const __half*)Av;
        for (int i = tid; i < 2048; i += 256) {
            int r = i >> 5, q = i & 31, c = q << 2;
            int row = row0 + r;
            uint2 v = make_uint2(0u, 0u);
            if (row < NN) v = *(const uint2*)(A + (size_t)row * FD + c);
            *(uint2*)(sm + OFF_A + (r * GP + c) * 2) = v;
        }
    } else {
        const float* A = (const float*)Av;
        for (int i = tid; i < 2048; i += 256) {
            int r = i >> 5, q = i & 31, c = q << 2;
            int row = row0 + r;
            float4 v = make_float4(0.f, 0.f, 0.f, 0.f);
            if (row < NN) {
                v = ((const float4*)A)[(size_t)row * 32 + q];
                if (SCALE) {
                    float s = rowscale[row];
                    v.x *= s; v.y *= s; v.z *= s; v.w *= s;
                }
            }
            *(uint2*)(sm + OFF_A + (r * GP + c) * 2) =
                make_uint2(f2h(v.x, v.y), f2h(v.z, v.w));
        }
    }
    // stage B
    for (int i = tid; i < 2048; i += 256) {
        int n = i >> 4, q = i & 15, c = q << 3;
        *(uint4*)(sm + OFF_B + (n * GP + c) * 2) = *(const uint4*)(B + n * FD + c);
    }
    __syncthreads();

    float acc[2][4][4];
    #pragma unroll
    for (int mt = 0; mt < 2; ++mt)
        #pragma unroll
        for (int nt = 0; nt < 4; ++nt)
            #pragma unroll
            for (int i = 0; i < 4; ++i) acc[mt][nt][i] = 0.0f;

    const uint32_t sbase = (uint32_t)__cvta_generic_to_shared(sm);
    const int arow = lane & 15;
    const int acol = (lane & 16) ? 8 : 0;
    const int brow = ((lane & 16) >> 1) + (lane & 7);
    const int bcol = (lane & 8) ? 8 : 0;
    const uint32_t aaddr = sbase + OFF_A + (((m0 + arow) * GP) + acol) * 2;
    const uint32_t baddr = sbase + OFF_B + (((n0 + brow) * GP) + bcol) * 2;

    #pragma unroll 2
    for (int ks = 0; ks < 8; ++ks) {
        uint32_t ko = (uint32_t)(ks << 5);
        uint32_t ah[2][4], bb[2][4];
        ldsm4(ah[0], aaddr + ko);
        ldsm4(ah[1], aaddr + ko + 16 * GP * 2);
        ldsm4(bb[0], baddr + ko);
        ldsm4(bb[1], baddr + ko + 16 * GP * 2);
        #pragma unroll
        for (int nt = 0; nt < 4; ++nt) {
            uint32_t b0 = bb[nt >> 1][(nt & 1) << 1];
            uint32_t b1 = bb[nt >> 1][((nt & 1) << 1) + 1];
            #pragma unroll
            for (int mt = 0; mt < 2; ++mt)
                mma_f16(acc[mt][nt], ah[mt], b0, b1);
        }
    }

    if (EPI == 0) {
        #pragma unroll
        for (int mt = 0; mt < 2; ++mt)
            #pragma unroll
            for (int nt = 0; nt < 4; ++nt) {
                int row = row0 + m0 + (mt << 4) + lr;
                int col = n0 + (nt << 3) + (lc << 1);
                float v0 = acc[mt][nt][0], v1 = acc[mt][nt][1];
                float v2 = acc[mt][nt][2], v3 = acc[mt][nt][3];
                if (OSC) {
                    float s0 = (row < NN) ? oscale[row] : 0.f;
                    float s1 = (row + 8 < NN) ? oscale[row + 8] : 0.f;
                    v0 *= s0; v1 *= s0; v2 *= s1; v3 *= s1;
                }
                if (OUTH) {
                    __half* Out = (__half*)OutV;
                    if (row < NN)
                        *(uint32_t*)&Out[(size_t)row * FD + col] = f2h(v0, v1);
                    if (row + 8 < NN)
                        *(uint32_t*)&Out[(size_t)(row + 8) * FD + col] = f2h(v2, v3);
                } else {
                    float* Out = (float*)OutV;
                    if (row < NN)
                        *(float2*)&Out[(size_t)row * FD + col] = make_float2(v0, v1);
                    if (row + 8 < NN)
                        *(float2*)&Out[(size_t)(row + 8) * FD + col] = make_float2(v2, v3);
                }
            }
    } else {
        float* Out = (float*)OutV;
        float* stg = (float*)sm;
        __syncthreads();
        #pragma unroll
        for (int mt = 0; mt < 2; ++mt)
            #pragma unroll
            for (int nt = 0; nt < 4; ++nt) {
                int rl = m0 + (mt << 4) + lr;
                int row = row0 + rl;
                int col = n0 + (nt << 3) + (lc << 1);
                float v0 = acc[mt][nt][0], v1 = acc[mt][nt][1];
                float v2 = acc[mt][nt][2], v3 = acc[mt][nt][3];
                if (ADDC) {
                    if (row < NN) {
                        float2 p = h2f(*(const uint32_t*)&C0[(size_t)row * FD + col]);
                        v0 += p.x; v1 += p.y;
                    }
                    if (row + 8 < NN) {
                        float2 p = h2f(*(const uint32_t*)&C0[(size_t)(row + 8) * FD + col]);
                        v2 += p.x; v3 += p.y;
                    }
                }
                float b0 = bias[col], b1 = bias[col + 1];
                stg[rl * SP + col]           = fmaxf(v0 + b0, 0.f);
                stg[rl * SP + col + 1]       = fmaxf(v1 + b1, 0.f);
                stg[(rl + 8) * SP + col]     = fmaxf(v2 + b0, 0.f);
                stg[(rl + 8) * SP + col + 1] = fmaxf(v3 + b1, 0.f);
            }
        __syncthreads();
        const float4* Wo4 = (const float4*)Wo;
        float4 w0 = Wo4[lane * 2];
        float4 w1 = Wo4[lane * 2 + 1];
        float ob0 = bo[0], ob1 = bo[1];
        #pragma unroll
        for (int rr = 0; rr < 8; ++rr) {
            int rl = (wid << 3) + rr;
            int row = row0 + rl;
            float4 h = *(float4*)&stg[rl * SP + (lane << 2)];
            float s0 = h.x * w0.x + h.y * w0.z + h.z * w1.x + h.w * w1.z;
            float s1 = h.x * w0.y + h.y * w0.w + h.z * w1.y + h.w * w1.w;
            #pragma unroll
            for (int off = 16; off; off >>= 1) {
                s0 += __shfl_down_sync(0xffffffffu, s0, off);
                s1 += __shfl_down_sync(0xffffffffu, s1, off);
            }
            if (lane == 0 && row < NN)
                *(float2*)&Out[2 * row] = make_float2(s0 + ob0, s1 + ob1);
        }
    }
}

// ---------------------------------------------------------------------------
// quad-paired gathers: 4 groups of 8 lanes process 4 edges concurrently.
// each lane covers halfs [hl*8..hl*8+7] and [64+hl*8..64+hl*8+7] (acc[16]);
// combine groups via shfl_down(8) then shfl_down(16); lanes 0-7 write.
// ---------------------------------------------------------------------------
template<bool PRESCALED>
__global__ void k_gcn_agg(const __half* __restrict__ Hsrc,
                          const float* __restrict__ bias, __half* __restrict__ dst) {
    int g = blockIdx.x * 256 + threadIdx.x;
    int n = g >> 5, lane = g & 31;
    if (n >= NN) return;
    const uint4* H4 = (const uint4*)Hsrc;
    int g4 = lane >> 3, hl = lane & 7;
    float dn = g_dis[n];
    float acc[16];
    #pragma unroll
    for (int k = 0; k < 16; ++k) acc[k] = 0.f;
    if (g4 == 0) {
        float sw = PRESCALED ? 1.0f : dn;
        acc8(acc,     H4[(size_t)n * 16 + hl],     sw);
        acc8(acc + 8, H4[(size_t)n * 16 + 8 + hl], sw);
    }
    int cnt = min(g_ecnt[n], ECAP);
    for (int b = 0; b < cnt; b += 32) {
        int m = min(cnt - b, 32);
        int r = 0; float w = 0.f;
        if (lane < m) {
            int2 e = g_ebkt[(size_t)n * ECAP + b + lane];
            r = e.x;
            w = __int_as_float(e.y);
            if (!PRESCALED) w *= g_dis[r];
        }
        for (int j = 0; j < m; j += 4) {
            int jj = j + g4;
            int   rj = __shfl_sync(0xffffffffu, r, jj);
            float wj = __shfl_sync(0xffffffffu, w, jj);
            if (jj < m) {
                acc8(acc,     H4[(size_t)rj * 16 + hl],     wj);
                acc8(acc + 8, H4[(size_t)rj * 16 + 8 + hl], wj);
            }
        }
    }
    #pragma unroll
    for (int k = 0; k < 16; ++k) {
        acc[k] += __shfl_down_sync(0xffffffffu, acc[k], 8);
        acc[k] += __shfl_down_sync(0xffffffffu, acc[k], 16);
    }
    if (g4 == 0) {
        #pragma unroll
        for (int hseg = 0; hseg < 2; ++hseg) {
            int c = (hl << 3) + hseg * 64;
            float* a = acc + hseg * 8;
            float4 b0 = *(const float4*)&bias[c];
            float4 b1 = *(const float4*)&bias[c + 4];
            uint4 o;
            o.x = f2h(fmaxf(dn * a[0] + b0.x, 0.f), fmaxf(dn * a[1] + b0.y, 0.f));
            o.y = f2h(fmaxf(dn * a[2] + b0.z, 0.f), fmaxf(dn * a[3] + b0.w, 0.f));
            o.z = f2h(fmaxf(dn * a[4] + b1.x, 0.f), fmaxf(dn * a[5] + b1.y, 0.f));
            o.w = f2h(fmaxf(dn * a[6] + b1.z, 0.f), fmaxf(dn * a[7] + b1.w, 0.f));
            *(uint4*)&dst[(size_t)n * FD + c] = o;
        }
    }
}

__global__ void k_he_agg(const __half* __restrict__ Hsrc) {
    int g = blockIdx.x * 256 + threadIdx.x;
    int h = g >> 5, lane = g & 31;
    if (h >= NM) return;
    const uint4* H4 = (const uint4*)Hsrc;
    int g4 = lane >> 3, hl = lane & 7;
    float acc[16];
    #pragma unroll
    for (int k = 0; k < 16; ++k) acc[k] = 0.f;
    int cnt = min(g_hcnt[h], HCAP);
    for (int b = 0; b < cnt; b += 32) {
        int m = min(cnt - b, 32);
        int nidx = 0;
        if (lane < m) nidx = g_hbkt[(size_t)h * HCAP + b + lane];
        for (int j = 0; j < m; j += 4) {
            int jj = j + g4;
            int nj = __shfl_sync(0xffffffffu, nidx, jj);
            if (jj < m) {
                acc8(acc,     H4[(size_t)nj * 16 + hl],     1.0f);
                acc8(acc + 8, H4[(size_t)nj * 16 + 8 + hl], 1.0f);
            }
        }
    }
    #pragma unroll
    for (int k = 0; k < 16; ++k) {
        acc[k] += __shfl_down_sync(0xffffffffu, acc[k], 8);
        acc[k] += __shfl_down_sync(0xffffffffu, acc[k], 16);
    }
    if (g4 == 0) {
        float w = g_Binv[h];
        #pragma unroll
        for (int hseg = 0; hseg < 2; ++hseg) {
            int c = (hl << 3) + hseg * 64;
            float* a = acc + hseg * 8;
            uint4 o;
            o.x = f2h(a[0] * w, a[1] * w);
            o.y = f2h(a[2] * w, a[3] * w);
            o.z = f2h(a[4] * w, a[5] * w);
            o.w = f2h(a[6] * w, a[7] * w);
            *(uint4*)&g_EFh[(size_t)h * FD + c] = o;
        }
    }
}

__global__ void k_node_agg(const float* __restrict__ bias, __half* __restrict__ dst) {
    int g = blockIdx.x * 256 + threadIdx.x;
    int n = g >> 5, lane = g & 31;
    if (n >= NN) return;
    const uint4* E4 = (const uint4*)g_EFh;
    int g4 = lane >> 3, hl = lane & 7;
    float acc[16];
    #pragma unroll
    for (int k = 0; k < 16; ++k) acc[k] = 0.f;
    int cnt = min(g_ncnt[n], NCAP);
    for (int b = 0; b < cnt; b += 32) {
        int m = min(cnt - b, 32);
        int hidx = 0;
        if (lane < m) hidx = g_nbkt[(size_t)n * NCAP + b + lane];
        for (int j = 0; j < m; j += 4) {
            int jj = j + g4;
            int hj = __shfl_sync(0xffffffffu, hidx, jj);
            if (jj < m) {
                acc8(acc,     E4[(size_t)hj * 16 + hl],     1.0f);
                acc8(acc + 8, E4[(size_t)hj * 16 + 8 + hl], 1.0f);
            }
        }
    }
    #pragma unroll
    for (int k = 0; k < 16; ++k) {
        acc[k] += __shfl_down_sync(0xffffffffu, acc[k], 8);
        acc[k] += __shfl_down_sync(0xffffffffu, acc[k], 16);
    }
    if (g4 == 0) {
        float w = g_Dinv[n];
        #pragma unroll
        for (int hseg = 0; hseg < 2; ++hseg) {
            int c = (hl << 3) + hseg * 64;
            float* a = acc + hseg * 8;
            float4 b0 = *(const float4*)&bias[c];
            float4 b1 = *(const float4*)&bias[c + 4];
            uint4 o;
            o.x = f2h(fmaxf(a[0] * w + b0.x, 0.f), fmaxf(a[1] * w + b0.y, 0.f));
            o.y = f2h(fmaxf(a[2] * w + b0.z, 0.f), fmaxf(a[3] * w + b0.w, 0.f));
            o.z = f2h(fmaxf(a[4] * w + b1.x, 0.f), fmaxf(a[5] * w + b1.y, 0.f));
            o.w = f2h(fmaxf(a[6] * w + b1.z, 0.f), fmaxf(a[7] * w + b1.w, 0.f));
            *(uint4*)&dst[(size_t)n * FD + c] = o;
        }
    }
}

// ---------------------------------------------------------------------------
// launch (R13 2-stream schedule + dis-fold)
// ---------------------------------------------------------------------------
extern "C" void kernel_launch(void* const* d_in, const int* /*in_sizes*/, int /*n_in*/,
                              void* d_out, int /*out_size*/) {
    const float* x   = (const float*)d_in[0];
    const int*   ei  = (const int*)  d_in[1];
    const float* ew  = (const float*)d_in[2];
    const int*   hei = (const int*)  d_in[3];
    const float* hd  = (const float*)d_in[4];
    const float* Wg1 = (const float*)d_in[5];  const float* bg1 = (const float*)d_in[6];
    const float* Wg2 = (const float*)d_in[7];  const float* bg2 = (const float*)d_in[8];
    const float* Wh1 = (const float*)d_in[9];  const float* bh1 = (const float*)d_in[10];
    const float* Wh2 = (const float*)d_in[11]; const float* bh2 = (const float*)d_in[12];
    const float* Wfc = (const float*)d_in[13]; const float* bfc = (const float*)d_in[14];
    const float* Wo  = (const float*)d_in[15]; const float* bo  = (const float*)d_in[16];
    float* out = (float*)d_out;

    const int* erow = ei;
    const int* ecol = ei + NE;
    const int* ni   = hei;
    const int* hi   = hei + NI;

    void *pHh, *pH2h, *pPART, *pX1, *pX2, *pNHW, *pDIS, *pW;
    cudaGetSymbolAddress(&pHh,  g_Hh);   cudaGetSymbolAddress(&pH2h, g_H2h);
    cudaGetSymbolAddress(&pPART, g_PARTh);
    cudaGetSymbolAddress(&pX1,  g_X1h);  cudaGetSymbolAddress(&pX2,  g_X2h);
    cudaGetSymbolAddress(&pNHW, g_nhw);  cudaGetSymbolAddress(&pDIS, g_dis);
    cudaGetSymbolAddress(&pW,   g_Wt);

    __half* Hh   = (__half*)pHh;
    __half* H2h  = (__half*)pH2h;
    __half* PART = (__half*)pPART;
    __half* X1   = (__half*)pX1;
    __half* X2   = (__half*)pX2;
    const float* NHW = (const float*)pNHW;
    const float* DIS = (const float*)pDIS;
    const __half* W = (const __half*)pW;

    cudaFuncSetAttribute((const void*)k_gemm<0, false, false, true,  false, false>, cudaFuncAttributeMaxDynamicSharedMemorySize, GSMEM);
    cudaFuncSetAttribute((const void*)k_gemm<0, true,  false, true,  false, false>, cudaFuncAttributeMaxDynamicSharedMemorySize, GSMEM);
    cudaFuncSetAttribute((const void*)k_gemm<0, false, false, true,  true,  false>, cudaFuncAttributeMaxDynamicSharedMemorySize, GSMEM);
    cudaFuncSetAttribute((const void*)k_gemm<0, false, false, true,  true,  true >, cudaFuncAttributeMaxDynamicSharedMemorySize, GSMEM);
    cudaFuncSetAttribute((const void*)k_gemm<3, false, true,  false, true,  false>, cudaFuncAttributeMaxDynamicSharedMemorySize, GSMEM);

    const int GB  = (NN + 63) / 64;
    const int NWG = (NN * 32 + 255) / 256;
    const int MWG = (NM * 32 + 255) / 256;
    const int NB  = (NN + 255) / 256;

    cudaStream_t s0 = 0;
    cudaStream_t s1 = g_si.ok ? g_si.s1 : (cudaStream_t)0;
    const bool dual = g_si.ok;

    if (dual) {
        cudaEventRecord(g_si.evFork, s0);
        cudaStreamWaitEvent(s1, g_si.evFork, 0);
    }

    // launch order: host-order #3 is the big GEMM (ncu -s window)
    k_wconv<<<(6 * FD * FD + 255) / 256, 256, 0, s0>>>(Wg1, Wg2, Wh1, Wh2, Wfc);   // #0
    if (dual) cudaEventRecord(g_si.evW, s0);
    k_init<<<NB, 256, 0, s1>>>();                                                  // #1
    k_build<<<(NE + NI + 255) / 256, 256, 0, s1>>>(erow, ecol, ew, ni, hi);        // #2
    k_gemm<0, false, false, true, false, false><<<GB, 256, GSMEM, s0>>>(           // #3 (profiled)
        x, W + 0 * FD * FD, nullptr, nullptr, nullptr, Hh, nullptr, nullptr, nullptr);
    k_prep_fin<<<NB, 256, 0, s1>>>(hd);                                            // #4
    if (dual) cudaEventRecord(g_si.evCSR, s1);

    // ---- stream1: hyper branch ----
    if (dual) cudaStreamWaitEvent(s1, g_si.evW, 0);
    k_gemm<0, true, false, true, false, false><<<GB, 256, GSMEM, s1>>>(
        x, W + 2 * FD * FD, NHW, nullptr, nullptr, H2h, nullptr, nullptr, nullptr);
    k_he_agg<<<MWG, 256, 0, s1>>>(H2h);
    k_node_agg<<<NWG, 256, 0, s1>>>(bh1, X2);
    k_gemm<0, false, false, true, true, false><<<GB, 256, GSMEM, s1>>>(
        X2, W + 3 * FD * FD, nullptr, nullptr, nullptr, H2h, nullptr, nullptr, nullptr);
    k_he_agg<<<MWG, 256, 0, s1>>>(H2h);
    k_node_agg<<<NWG, 256, 0, s1>>>(bh2, X2);
    if (dual) cudaEventRecord(g_si.evHyp, s1);

    // ---- stream0: GCN branch ----
    if (dual) cudaStreamWaitEvent(s0, g_si.evCSR, 0);
    k_gcn_agg<false><<<NWG, 256, 0, s0>>>(Hh, bg1, X1);
    // gemm2 scales output rows by dis -> gather2 reads pre-scaled rows
    k_gemm<0, false, false, true, true, true><<<GB, 256, GSMEM, s0>>>(
        X1, W + 1 * FD * FD, nullptr, nullptr, nullptr, Hh, nullptr, nullptr, DIS);
    k_gcn_agg<true><<<NWG, 256, 0, s0>>>(Hh, bg2, X1);

    // ---- FC pass A (fp16 PART) ----
    k_gemm<0, false, false, true, true, false><<<GB, 256, GSMEM, s0>>>(
        X1, W + 4 * FD * FD, nullptr, nullptr, nullptr, PART, nullptr, nullptr, nullptr);

    // ---- join + FC pass B with fused out head ----
    if (dual) cudaStreamWaitEvent(s0, g_si.evHyp, 0);
    k_gemm<3, false, true, false, true, false><<<GB, 256, GSMEM, s0>>>(
        X2, W + 5 * FD * FD, nullptr, bfc, PART, out, Wo, bo, nullptr);
}

// round 16
// speedup vs baseline: 1.5230x; 1.5230x over previous
#include <cuda_runtime.h>
#include <cuda_fp16.h>
#include <cstdint>

// ---------------------------------------------------------------------------
// CompositeGraphNetWithFC on GB300 (sm_103 PTX -> mma.sync HMMA)
// R16: R13 gathers (half-warp paired) + dis-fold + dual-output first GEMM
//      (A staged once for Wg1 and Wh1; nhw moved into he_agg).
// ---------------------------------------------------------------------------

#define NN 100000
#define NE 1600000
#define NM 10000
#define NI 800000
#define FD 128

#define ECAP 64
#define HCAP 160
#define NCAP 40

// ---- scratch ----
__device__ __align__(16) __half g_Hh [(size_t)NN * FD];
__device__ __align__(16) __half g_H2h[(size_t)NN * FD];
__device__ __align__(16) __half g_EFh[(size_t)NM * FD];
__device__ __align__(16) __half g_X1h[(size_t)NN * FD];
__device__ __align__(16) __half g_X2h[(size_t)NN * FD];
__device__ __align__(16) __half g_PARTh[(size_t)NN * FD];
__device__ float g_dis [NN];
__device__ float g_nhw [NN];
__device__ float g_Dinv[NN];
__device__ float g_Binv[NM];
__device__ int   g_ecnt[NN], g_hcnt[NM], g_ncnt[NN];
__device__ __align__(8) int2 g_ebkt[(size_t)NN * ECAP];
__device__ int   g_hbkt[(size_t)NM * HCAP];
__device__ int   g_nbkt[(size_t)NN * NCAP];
__device__ __align__(16) __half g_Wt[6 * FD * FD];

struct StreamInit {
    cudaStream_t s1 = 0;
    cudaEvent_t evFork = 0, evG = 0, evCSR = 0, evHyp = 0;
    bool ok = false;
    StreamInit() {
        ok = (cudaStreamCreateWithFlags(&s1, cudaStreamNonBlocking) == cudaSuccess)
          && (cudaEventCreateWithFlags(&evFork, cudaEventDisableTiming) == cudaSuccess)
          && (cudaEventCreateWithFlags(&evG,    cudaEventDisableTiming) == cudaSuccess)
          && (cudaEventCreateWithFlags(&evCSR,  cudaEventDisableTiming) == cudaSuccess)
          && (cudaEventCreateWithFlags(&evHyp,  cudaEventDisableTiming) == cudaSuccess);
        if (!ok) s1 = 0;
    }
};
static StreamInit g_si;

__device__ __forceinline__ float2 h2f(uint32_t u) {
    return __half22float2(*reinterpret_cast<__half2*>(&u));
}
__device__ __forceinline__ uint32_t f2h(float a, float b) {
    __half2 h = __floats2half2_rn(a, b);
    return *reinterpret_cast<uint32_t*>(&h);
}
__device__ __forceinline__ void acc8(float* acc, uint4 u, float w) {
    float2 p0 = h2f(u.x), p1 = h2f(u.y), p2 = h2f(u.z), p3 = h2f(u.w);
    acc[0] += w * p0.x; acc[1] += w * p0.y;
    acc[2] += w * p1.x; acc[3] += w * p1.y;
    acc[4] += w * p2.x; acc[5] += w * p2.y;
    acc[6] += w * p3.x; acc[7] += w * p3.y;
}

// ---------------------------------------------------------------------------
// weight conversion
// ---------------------------------------------------------------------------
__global__ void k_wconv(const float* __restrict__ Wg1, const float* __restrict__ Wg2,
                        const float* __restrict__ Wh1, const float* __restrict__ Wh2,
                        const float* __restrict__ Wfc) {
    int idx = blockIdx.x * 256 + threadIdx.x;
    if (idx >= 6 * FD * FD) return;
    int b = idx >> 14, e = idx & 16383, n = e >> 7, k = e & 127;
    float w;
    switch (b) {
        case 0: w = Wg1[k * FD + n]; break;
        case 1: w = Wg2[k * FD + n]; break;
        case 2: w = Wh1[k * FD + n]; break;
        case 3: w = Wh2[k * FD + n]; break;
        case 4: w = Wfc[k * FD + n]; break;
        default: w = Wfc[(k + FD) * FD + n]; break;
    }
    g_Wt[idx] = __float2half_rn(w);
}

// ---------------------------------------------------------------------------
// prep
// ---------------------------------------------------------------------------
__global__ void k_init() {
    int i = blockIdx.x * 256 + threadIdx.x;
    if (i < NN) { g_ecnt[i] = 0; g_ncnt[i] = 0; }
    if (i < NM) { g_hcnt[i] = 0; }
}
__global__ void k_build(const int* __restrict__ erow, const int* __restrict__ ecol,
                        const float* __restrict__ ew,
                        const int* __restrict__ ni, const int* __restrict__ hi) {
    int idx = blockIdx.x * 256 + threadIdx.x;
    if (idx < NE) {
        int r = erow[idx], c = ecol[idx];
        float w = ew[idx];
        int p = atomicAdd(&g_ecnt[c], 1);
        if (p < ECAP) g_ebkt[(size_t)c * ECAP + p] = make_int2(r, __float_as_int(w));
    } else if (idx < NE + NI) {
        int i = idx - NE;
        int n = ni[i], h = hi[i];
        int p = atomicAdd(&g_hcnt[h], 1);
        if (p < HCAP) g_hbkt[(size_t)h * HCAP + p] = n;
        int q = atomicAdd(&g_ncnt[n], 1);
        if (q < NCAP) g_nbkt[(size_t)n * NCAP + q] = h;
    }
}
__global__ void k_prep_fin(const float* __restrict__ hd) {
    int i = blockIdx.x * 256 + threadIdx.x;
    if (i < NN) {
        int ec = min(g_ecnt[i], ECAP);
        float deg = 1.0f;
        for (int j = 0; j < ec; ++j)
            deg += __int_as_float(g_ebkt[(size_t)i * ECAP + j].y);
        g_dis[i] = rsqrtf(deg);
        int nc_raw = g_ncnt[i];
        int nc = min(nc_raw, NCAP);
        float nh = 0.0f;
        for (int j = 0; j < nc; ++j)
            nh += hd[g_nbkt[(size_t)i * NCAP + j]];
        g_nhw[i] = nh;
        g_Dinv[i] = nc_raw > 0 ? 1.0f / (float)nc_raw : 0.0f;
    }
    if (i < NM) {
        int b = g_hcnt[i];
        g_Binv[i] = b > 0 ? 1.0f / (float)b : 0.0f;
    }
}

// ---------------------------------------------------------------------------
// GEMM core (64-row tile x 128, single-product fp16 mma + ldmatrix)
// ---------------------------------------------------------------------------
#define GP 136
#define OFF_A 0
#define OFF_B (64 * GP * 2)
#define GSMEM (OFF_B + 128 * GP * 2)    // 52224 bytes
#define SP 132

__device__ __forceinline__ void mma_f16(float* d, const uint32_t* a,
                                        uint32_t b0, uint32_t b1) {
    asm volatile(
        "mma.sync.aligned.m16n8k16.row.col.f32.f16.f16.f32 "
        "{%0,%1,%2,%3}, {%4,%5,%6,%7}, {%8,%9}, {%0,%1,%2,%3};"
        : "+f"(d[0]), "+f"(d[1]), "+f"(d[2]), "+f"(d[3])
        : "r"(a[0]), "r"(a[1]), "r"(a[2]), "r"(a[3]), "r"(b0), "r"(b1));
}
__device__ __forceinline__ void ldsm4(uint32_t* r, uint32_t a) {
    asm volatile("ldmatrix.sync.aligned.m8n8.x4.shared.b16 {%0,%1,%2,%3}, [%4];"
                 : "=r"(r[0]), "=r"(r[1]), "=r"(r[2]), "=r"(r[3]) : "r"(a));
}
__device__ __forceinline__ void stage_Bbuf(char* sm, int tid, const __half* __restrict__ B) {
    for (int i = tid; i < 2048; i += 256) {
        int n = i >> 4, q = i & 15, c = q << 3;
        *(uint4*)(sm + OFF_B + (n * GP + c) * 2) = *(const uint4*)(B + n * FD + c);
    }
}
__device__ __forceinline__ void mma_mainloop(char* sm, float (*acc)[4][4],
                                             uint32_t aaddr, uint32_t baddr) {
    #pragma unroll 2
    for (int ks = 0; ks < 8; ++ks) {
        uint32_t ko = (uint32_t)(ks << 5);
        uint32_t ah[2][4], bb[2][4];
        ldsm4(ah[0], aaddr + ko);
        ldsm4(ah[1], aaddr + ko + 16 * GP * 2);
        ldsm4(bb[0], baddr + ko);
        ldsm4(bb[1], baddr + ko + 16 * GP * 2);
        #pragma unroll
        for (int nt = 0; nt < 4; ++nt) {
            uint32_t b0 = bb[nt >> 1][(nt & 1) << 1];
            uint32_t b1 = bb[nt >> 1][((nt & 1) << 1) + 1];
            #pragma unroll
            for (int mt = 0; mt < 2; ++mt)
                mma_f16(acc[mt][nt], ah[mt], b0, b1);
        }
    }
}
__device__ __forceinline__ void epi_h16(float (*acc)[4][4], __half* Out,
                                        int row0, int m0, int n0, int lr, int lc) {
    #pragma unroll
    for (int mt = 0; mt < 2; ++mt)
        #pragma unroll
        for (int nt = 0; nt < 4; ++nt) {
            int row = row0 + m0 + (mt << 4) + lr;
            int col = n0 + (nt << 3) + (lc << 1);
            if (row < NN)
                *(uint32_t*)&Out[(size_t)row * FD + col] = f2h(acc[mt][nt][0], acc[mt][nt][1]);
            if (row + 8 < NN)
                *(uint32_t*)&Out[(size_t)(row + 8) * FD + col] = f2h(acc[mt][nt][2], acc[mt][nt][3]);
        }
}

// dual-output GEMM: C1 = A@B1, C2 = A@B2 (A staged once)
__global__ void __launch_bounds__(256, 4) k_gemm_dual(
    const float* __restrict__ A,
    const __half* __restrict__ B1, const __half* __restrict__ B2,
    __half* __restrict__ Out1, __half* __restrict__ Out2)
{
    extern __shared__ char sm[];
    const int tid = threadIdx.x, lane = tid & 31, wid = tid >> 5;
    const int row0 = blockIdx.x << 6;
    const int m0 = (wid & 1) << 5, n0 = (wid >> 1) << 5;
    const int lr = lane >> 2, lc = lane & 3;

    for (int i = tid; i < 2048; i += 256) {
        int r = i >> 5, q = i & 31, c = q << 2;
        int row = row0 + r;
        float4 v = make_float4(0.f, 0.f, 0.f, 0.f);
        if (row < NN) v = ((const float4*)A)[(size_t)row * 32 + q];
        *(uint2*)(sm + OFF_A + (r * GP + c) * 2) =
            make_uint2(f2h(v.x, v.y), f2h(v.z, v.w));
    }
    stage_Bbuf(sm, tid, B1);
    __syncthreads();

    const uint32_t sbase = (uint32_t)__cvta_generic_to_shared(sm);
    const int arow = lane & 15;
    const int acol = (lane & 16) ? 8 : 0;
    const int brow = ((lane & 16) >> 1) + (lane & 7);
    const int bcol = (lane & 8) ? 8 : 0;
    const uint32_t aaddr = sbase + OFF_A + (((m0 + arow) * GP) + acol) * 2;
    const uint32_t baddr = sbase + OFF_B + (((n0 + brow) * GP) + bcol) * 2;

    float acc[2][4][4];
    #pragma unroll
    for (int mt = 0; mt < 2; ++mt)
        #pragma unroll
        for (int nt = 0; nt < 4; ++nt)
            #pragma unroll
            for (int i = 0; i < 4; ++i) acc[mt][nt][i] = 0.0f;
    mma_mainloop(sm, acc, aaddr, baddr);
    epi_h16(acc, Out1, row0, m0, n0, lr, lc);

    __syncthreads();               // all warps done reading B1
    stage_Bbuf(sm, tid, B2);
    __syncthreads();
    #pragma unroll
    for (int mt = 0; mt < 2; ++mt)
        #pragma unroll
        for (int nt = 0; nt < 4; ++nt)
            #pragma unroll
            for (int i = 0; i < 4; ++i) acc[mt][nt][i] = 0.0f;
    mma_mainloop(sm, acc, aaddr, baddr);
    epi_h16(acc, Out2, row0, m0, n0, lr, lc);
}

// general GEMM (A fp16; EPI 0 store / EPI 3 FC tail; OSC row-scale)
template<int EPI, bool OSC>
__global__ void __launch_bounds__(256, 4) k_gemm(
    const __half* __restrict__ A,
    const __half* __restrict__ B,
    const float* __restrict__ bias,
    const __half* __restrict__ C0,
    void* __restrict__ OutV,
    const float* __restrict__ Wo, const float* __restrict__ bo,
    const float* __restrict__ oscale)
{
    extern __shared__ char sm[];
    const int tid = threadIdx.x, lane = tid & 31, wid = tid >> 5;
    const int row0 = blockIdx.x << 6;
    const int m0 = (wid & 1) << 5, n0 = (wid >> 1) << 5;
    const int lr = lane >> 2, lc = lane & 3;

    for (int i = tid; i < 2048; i += 256) {
        int r = i >> 5, q = i & 31, c = q << 2;
        int row = row0 + r;
        uint2 v = make_uint2(0u, 0u);
        if (row < NN) v = *(const uint2*)(A + (size_t)row * FD + c);
        *(uint2*)(sm + OFF_A + (r * GP + c) * 2) = v;
    }
    stage_Bbuf(sm, tid, B);
    __syncthreads();

    float acc[2][4][4];
    #pragma unroll
    for (int mt = 0; mt < 2; ++mt)
        #pragma unroll
        for (int nt = 0; nt < 4; ++nt)
            #pragma unroll
            for (int i = 0; i < 4; ++i) acc[mt][nt][i] = 0.0f;

    const uint32_t sbase = (uint32_t)__cvta_generic_to_shared(sm);
    const int arow = lane & 15;
    const int acol = (lane & 16) ? 8 : 0;
    const int brow = ((lane & 16) >> 1) + (lane & 7);
    const int bcol = (lane & 8) ? 8 : 0;
    const uint32_t aaddr = sbase + OFF_A + (((m0 + arow) * GP) + acol) * 2;
    const uint32_t baddr = sbase + OFF_B + (((n0 + brow) * GP) + bcol) * 2;

    mma_mainloop(sm, acc, aaddr, baddr);

    if (EPI == 0) {
        #pragma unroll
        for (int mt = 0; mt < 2; ++mt)
            #pragma unroll
            for (int nt = 0; nt < 4; ++nt) {
                int row = row0 + m0 + (mt << 4) + lr;
                int col = n0 + (nt << 3) + (lc << 1);
                float v0 = acc[mt][nt][0], v1 = acc[mt][nt][1];
                float v2 = acc[mt][nt][2], v3 = acc[mt][nt][3];
                if (OSC) {
                    float s0 = (row < NN) ? oscale[row] : 0.f;
                    float s1 = (row + 8 < NN) ? oscale[row + 8] : 0.f;
                    v0 *= s0; v1 *= s0; v2 *= s1; v3 *= s1;
                }
                __half* Out = (__half*)OutV;
                if (row < NN)
                    *(uint32_t*)&Out[(size_t)row * FD + col] = f2h(v0, v1);
                if (row + 8 < NN)
                    *(uint32_t*)&Out[(size_t)(row + 8) * FD + col] = f2h(v2, v3);
            }
    } else {
        float* Out = (float*)OutV;
        float* stg = (float*)sm;
        __syncthreads();
        #pragma unroll
        for (int mt = 0; mt < 2; ++mt)
            #pragma unroll
            for (int nt = 0; nt < 4; ++nt) {
                int rl = m0 + (mt << 4) + lr;
                int row = row0 + rl;
                int col = n0 + (nt << 3) + (lc << 1);
                float v0 = acc[mt][nt][0], v1 = acc[mt][nt][1];
                float v2 = acc[mt][nt][2], v3 = acc[mt][nt][3];
                if (row < NN) {
                    float2 p = h2f(*(const uint32_t*)&C0[(size_t)row * FD + col]);
                    v0 += p.x; v1 += p.y;
                }
                if (row + 8 < NN) {
                    float2 p = h2f(*(const uint32_t*)&C0[(size_t)(row + 8) * FD + col]);
                    v2 += p.x; v3 += p.y;
                }
                float b0 = bias[col], b1 = bias[col + 1];
                stg[rl * SP + col]           = fmaxf(v0 + b0, 0.f);
                stg[rl * SP + col + 1]       = fmaxf(v1 + b1, 0.f);
                stg[(rl + 8) * SP + col]     = fmaxf(v2 + b0, 0.f);
                stg[(rl + 8) * SP + col + 1] = fmaxf(v3 + b1, 0.f);
            }
        __syncthreads();
        const float4* Wo4 = (const float4*)Wo;
        float4 w0 = Wo4[lane * 2];
        float4 w1 = Wo4[lane * 2 + 1];
        float ob0 = bo[0], ob1 = bo[1];
        #pragma unroll
        for (int rr = 0; rr < 8; ++rr) {
            int rl = (wid << 3) + rr;
            int row = row0 + rl;
            float4 h = *(float4*)&stg[rl * SP + (lane << 2)];
            float s0 = h.x * w0.x + h.y * w0.z + h.z * w1.x + h.w * w1.z;
            float s1 = h.x * w0.y + h.y * w0.w + h.z * w1.y + h.w * w1.w;
            #pragma unroll
            for (int off = 16; off; off >>= 1) {
                s0 += __shfl_down_sync(0xffffffffu, s0, off);
                s1 += __shfl_down_sync(0xffffffffu, s1, off);
            }
            if (lane == 0 && row < NN)
                *(float2*)&Out[2 * row] = make_float2(s0 + ob0, s1 + ob1);
        }
    }
}

// ---------------------------------------------------------------------------
// half-warp-paired gathers (R13 structure)
// ---------------------------------------------------------------------------
template<bool PRESCALED>
__global__ void k_gcn_agg(const __half* __restrict__ Hsrc,
                          const float* __restrict__ bias, __half* __restrict__ dst) {
    int g = blockIdx.x * 256 + threadIdx.x;
    int n = g >> 5, lane = g & 31;
    if (n >= NN) return;
    const uint4* H4 = (const uint4*)Hsrc;
    int half = lane >> 4, hl = lane & 15;
    float dn = g_dis[n];
    float acc[8] = {0.f, 0.f, 0.f, 0.f, 0.f, 0.f, 0.f, 0.f};
    if (half == 0)
        acc8(acc, H4[(size_t)n * 16 + hl], PRESCALED ? 1.0f : dn);
    int cnt = min(g_ecnt[n], ECAP);
    for (int b = 0; b < cnt; b += 32) {
        int m = min(cnt - b, 32);
        int r = 0; float w = 0.f;
        if (lane < m) {
            int2 e = g_ebkt[(size_t)n * ECAP + b + lane];
            r = e.x;
            w = __int_as_float(e.y);
            if (!PRESCALED) w *= g_dis[r];
        }
        for (int j = 0; j < m; j += 2) {
            int jj = j + half;
            int   rj = __shfl_sync(0xffffffffu, r, jj);
            float wj = __shfl_sync(0xffffffffu, w, jj);
            if (jj < m)
                acc8(acc, H4[(size_t)rj * 16 + hl], wj);
        }
    }
    #pragma unroll
    for (int k = 0; k < 8; ++k)
        acc[k] += __shfl_down_sync(0xffffffffu, acc[k], 16);
    if (half == 0) {
        int c = hl << 3;
        float4 b0 = *(const float4*)&bias[c];
        float4 b1 = *(const float4*)&bias[c + 4];
        uint4 o;
        o.x = f2h(fmaxf(dn * acc[0] + b0.x, 0.f), fmaxf(dn * acc[1] + b0.y, 0.f));
        o.y = f2h(fmaxf(dn * acc[2] + b0.z, 0.f), fmaxf(dn * acc[3] + b0.w, 0.f));
        o.z = f2h(fmaxf(dn * acc[4] + b1.x, 0.f), fmaxf(dn * acc[5] + b1.y, 0.f));
        o.w = f2h(fmaxf(dn * acc[6] + b1.z, 0.f), fmaxf(dn * acc[7] + b1.w, 0.f));
        *(uint4*)&dst[(size_t)n * FD + c] = o;
    }
}

// SCALED: gathered rows weighted by nhw[node] (x-prescale moved here)
template<bool SCALED>
__global__ void k_he_agg(const __half* __restrict__ Hsrc) {
    int g = blockIdx.x * 256 + threadIdx.x;
    int h = g >> 5, lane = g & 31;
    if (h >= NM) return;
    const uint4* H4 = (const uint4*)Hsrc;
    int half = lane >> 4, hl = lane & 15;
    float acc[8] = {0.f, 0.f, 0.f, 0.f, 0.f, 0.f, 0.f, 0.f};
    int cnt = min(g_hcnt[h], HCAP);
    for (int b = 0; b < cnt; b += 32) {
        int m = min(cnt - b, 32);
        int nidx = 0; float wv = 1.0f;
        if (lane < m) {
            nidx = g_hbkt[(size_t)h * HCAP + b + lane];
            if (SCALED) wv = g_nhw[nidx];
        }
        for (int j = 0; j < m; j += 2) {
            int jj = j + half;
            int   nj = __shfl_sync(0xffffffffu, nidx, jj);
            float wj = SCALED ? __shfl_sync(0xffffffffu, wv, jj) : 1.0f;
            if (jj < m)
                acc8(acc, H4[(size_t)nj * 16 + hl], wj);
        }
    }
    #pragma unroll
    for (int k = 0; k < 8; ++k)
        acc[k] += __shfl_down_sync(0xffffffffu, acc[k], 16);
    if (half == 0) {
        float w = g_Binv[h];
        uint4 o;
        o.x = f2h(acc[0] * w, acc[1] * w);
        o.y = f2h(acc[2] * w, acc[3] * w);
        o.z = f2h(acc[4] * w, acc[5] * w);
        o.w = f2h(acc[6] * w, acc[7] * w);
        *(uint4*)&g_EFh[(size_t)h * FD + (hl << 3)] = o;
    }
}

__global__ void k_node_agg(const float* __restrict__ bias, __half* __restrict__ dst) {
    int g = blockIdx.x * 256 + threadIdx.x;
    int n = g >> 5, lane = g & 31;
    if (n >= NN) return;
    const uint4* E4 = (const uint4*)g_EFh;
    int half = lane >> 4, hl = lane & 15;
    float acc[8] = {0.f, 0.f, 0.f, 0.f, 0.f, 0.f, 0.f, 0.f};
    int cnt = min(g_ncnt[n], NCAP);
    for (int b = 0; b < cnt; b += 32) {
        int m = min(cnt - b, 32);
        int hidx = 0;
        if (lane < m) hidx = g_nbkt[(size_t)n * NCAP + b + lane];
        for (int j = 0; j < m; j += 2) {
            int jj = j + half;
            int hj = __shfl_sync(0xffffffffu, hidx, jj);
            if (jj < m)
                acc8(acc, E4[(size_t)hj * 16 + hl], 1.0f);
        }
    }
    #pragma unroll
    for (int k = 0; k < 8; ++k)
        acc[k] += __shfl_down_sync(0xffffffffu, acc[k], 16);
    if (half == 0) {
        float w = g_Dinv[n];
        int c = hl << 3;
        float4 b0 = *(const float4*)&bias[c];
        float4 b1 = *(const float4*)&bias[c + 4];
        uint4 o;
        o.x = f2h(fmaxf(acc[0] * w + b0.x, 0.f), fmaxf(acc[1] * w + b0.y, 0.f));
        o.y = f2h(fmaxf(acc[2] * w + b0.z, 0.f), fmaxf(acc[3] * w + b0.w, 0.f));
        o.z = f2h(fmaxf(acc[4] * w + b1.x, 0.f), fmaxf(acc[5] * w + b1.y, 0.f));
        o.w = f2h(fmaxf(acc[6] * w + b1.z, 0.f), fmaxf(acc[7] * w + b1.w, 0.f));
        *(uint4*)&dst[(size_t)n * FD + c] = o;
    }
}

// ---------------------------------------------------------------------------
// launch
// ---------------------------------------------------------------------------
extern "C" void kernel_launch(void* const* d_in, const int* /*in_sizes*/, int /*n_in*/,
                              void* d_out, int /*out_size*/) {
    const float* x   = (const float*)d_in[0];
    const int*   ei  = (const int*)  d_in[1];
    const float* ew  = (const float*)d_in[2];
    const int*   hei = (const int*)  d_in[3];
    const float* hd  = (const float*)d_in[4];
    const float* Wg1 = (const float*)d_in[5];  const float* bg1 = (const float*)d_in[6];
    const float* Wg2 = (const float*)d_in[7];  const float* bg2 = (const float*)d_in[8];
    const float* Wh1 = (const float*)d_in[9];  const float* bh1 = (const float*)d_in[10];
    const float* Wh2 = (const float*)d_in[11]; const float* bh2 = (const float*)d_in[12];
    const float* Wfc = (const float*)d_in[13]; const float* bfc = (const float*)d_in[14];
    const float* Wo  = (const float*)d_in[15]; const float* bo  = (const float*)d_in[16];
    float* out = (float*)d_out;

    const int* erow = ei;
    const int* ecol = ei + NE;
    const int* ni   = hei;
    const int* hi   = hei + NI;

    void *pHh, *pH2h, *pPART, *pX1, *pX2, *pDIS, *pW;
    cudaGetSymbolAddress(&pHh,  g_Hh);   cudaGetSymbolAddress(&pH2h, g_H2h);
    cudaGetSymbolAddress(&pPART, g_PARTh);
    cudaGetSymbolAddress(&pX1,  g_X1h);  cudaGetSymbolAddress(&pX2,  g_X2h);
    cudaGetSymbolAddress(&pDIS, g_dis);
    cudaGetSymbolAddress(&pW,   g_Wt);

    __half* Hh   = (__half*)pHh;
    __half* H2h  = (__half*)pH2h;
    __half* PART = (__half*)pPART;
    __half* X1   = (__half*)pX1;
    __half* X2   = (__half*)pX2;
    const float* DIS = (const float*)pDIS;
    const __half* W = (const __half*)pW;

    cudaFuncSetAttribute((const void*)k_gemm_dual,       cudaFuncAttributeMaxDynamicSharedMemorySize, GSMEM);
    cudaFuncSetAttribute((const void*)k_gemm<0, false>,  cudaFuncAttributeMaxDynamicSharedMemorySize, GSMEM);
    cudaFuncSetAttribute((const void*)k_gemm<0, true >,  cudaFuncAttributeMaxDynamicSharedMemorySize, GSMEM);
    cudaFuncSetAttribute((const void*)k_gemm<3, false>,  cudaFuncAttributeMaxDynamicSharedMemorySize, GSMEM);

    const int GB  = (NN + 63) / 64;
    const int NWG = (NN * 32 + 255) / 256;
    const int MWG = (NM * 32 + 255) / 256;
    const int NB  = (NN + 255) / 256;

    cudaStream_t s0 = 0;
    cudaStream_t s1 = g_si.ok ? g_si.s1 : (cudaStream_t)0;
    const bool dual = g_si.ok;

    if (dual) {
        cudaEventRecord(g_si.evFork, s0);
        cudaStreamWaitEvent(s1, g_si.evFork, 0);
    }

    // ---- s0: weights + dual first GEMM (x -> Hh, H2raw); s1: prep ----
    k_wconv<<<(6 * FD * FD + 255) / 256, 256, 0, s0>>>(Wg1, Wg2, Wh1, Wh2, Wfc);   // #0
    k_init<<<NB, 256, 0, s1>>>();                                                  // #1
    k_build<<<(NE + NI + 255) / 256, 256, 0, s1>>>(erow, ecol, ew, ni, hi);        // #2
    k_gemm_dual<<<GB, 256, GSMEM, s0>>>(x, W + 0 * FD * FD, W + 2 * FD * FD,       // #3 (profiled)
                                        Hh, H2h);
    if (dual) cudaEventRecord(g_si.evG, s0);
    k_prep_fin<<<NB, 256, 0, s1>>>(hd);                                            // #4
    if (dual) cudaEventRecord(g_si.evCSR, s1);

    // ---- s1: hyper branch (he_agg applies nhw to gathered rows) ----
    if (dual) cudaStreamWaitEvent(s1, g_si.evG, 0);
    k_he_agg<true><<<MWG, 256, 0, s1>>>(H2h);
    k_node_agg<<<NWG, 256, 0, s1>>>(bh1, X2);
    k_gemm<0, false><<<GB, 256, GSMEM, s1>>>(
        X2, W + 3 * FD * FD, nullptr, nullptr, H2h, nullptr, nullptr, nullptr);
    k_he_agg<false><<<MWG, 256, 0, s1>>>(H2h);
    k_node_agg<<<NWG, 256, 0, s1>>>(bh2, X2);
    if (dual) cudaEventRecord(g_si.evHyp, s1);

    // ---- s0: GCN branch ----
    if (dual) cudaStreamWaitEvent(s0, g_si.evCSR, 0);
    k_gcn_agg<false><<<NWG, 256, 0, s0>>>(Hh, bg1, X1);
    // gemm2 scales output rows by dis -> gather2 reads pre-scaled rows
    k_gemm<0, true><<<GB, 256, GSMEM, s0>>>(
        X1, W + 1 * FD * FD, nullptr, nullptr, Hh, nullptr, nullptr, DIS);
    k_gcn_agg<true><<<NWG, 256, 0, s0>>>(Hh, bg2, X1);

    // ---- FC pass A (fp16 PART) ----
    k_gemm<0, false><<<GB, 256, GSMEM, s0>>>(
        X1, W + 4 * FD * FD, nullptr, nullptr, PART, nullptr, nullptr, nullptr);

    // ---- join + FC pass B with fused out head ----
    if (dual) cudaStreamWaitEvent(s0, g_si.evHyp, 0);
    k_gemm<3, false><<<GB, 256, GSMEM, s0>>>(
        X2, W + 5 * FD * FD, bfc, PART, out, Wo, bo, nullptr);
}